// round 1
// baseline (speedup 1.0000x reference)
#include <cuda_runtime.h>
#include <math.h>

#define NNODE 50000
#define EMB 35
#define DEG 32
#define NBSTRIDE 40   // padded row: 35 ch + s_b slot unused + pad -> 160B, 32B aligned

// ---------------- scratch (device globals; no runtime allocation) ----------------
__device__ float g_nb[4][NNODE * NBSTRIDE];  // transformed neighbor embeddings (padded rows)
__device__ float g_sb[4][NNODE];             // per-node dst-side attention score
__device__ float g_sa[4][NNODE];             // per-node src-side attention score
__device__ float g_m [4][NNODE * EMB];       // aggregation results

// ---------------- packed f32x2 helpers ----------------
static __device__ __forceinline__ unsigned long long pack2(float a, float b) {
    unsigned long long r;
    unsigned int lo = __float_as_uint(a), hi = __float_as_uint(b);
    asm("mov.b64 %0, {%1, %2};" : "=l"(r) : "r"(lo), "r"(hi));
    return r;
}
static __device__ __forceinline__ void unpack2(unsigned long long v, float &a, float &b) {
    unsigned int lo, hi;
    asm("mov.b64 {%0, %1}, %2;" : "=r"(lo), "=r"(hi) : "l"(v));
    a = __uint_as_float(lo);
    b = __uint_as_float(hi);
}
#define FMA2(d, a, b, c) \
    asm("fma.rn.f32x2 %0, %1, %2, %3;" : "=l"(d) : "l"(a), "l"(b), "l"(c))

// ---------------- kernel args ----------------
struct TArgs {
    const float* fsrc[4];  // features that get transformed (neighbor side)
    const float* fdst[4];  // features on the aggregating side (for s_a)
    const float* W[4];
    const float* b[4];
    const float* att[4];
};
struct AArgs {
    const int* dst[4];
};

// =====================================================================
// Kernel 1: nb = fsrc @ W + b ; s_b = nb @ att[35:70] ; s_a = fdst @ att[0:35]
// thread per row, 4 jobs on gridDim.y
// =====================================================================
__global__ __launch_bounds__(128) void transform_kernel(TArgs args) {
    const int jid = blockIdx.y;
    const float* __restrict__ fsrc = args.fsrc[jid];
    const float* __restrict__ fdst = args.fdst[jid];
    const float* __restrict__ W    = args.W[jid];
    const float* __restrict__ bv   = args.b[jid];
    const float* __restrict__ att  = args.att[jid];

    __shared__ __align__(16) float Wsh[EMB * 36];          // rows padded to 36
    __shared__ __align__(16) unsigned long long bp[18];    // packed bias (pad 0)
    __shared__ __align__(16) unsigned long long ahp[18];   // packed att-hi (pad 0)
    __shared__ __align__(16) float alo[EMB];

    const int tid = threadIdx.x;
    for (int i = tid; i < EMB * 36; i += blockDim.x) {
        int k = i / 36, c = i % 36;
        Wsh[i] = (c < EMB) ? W[k * EMB + c] : 0.0f;
    }
    if (tid < 18) {
        int c = 2 * tid;
        float b0 = bv[c];
        float b1 = (c + 1 < EMB) ? bv[c + 1] : 0.0f;
        bp[tid] = pack2(b0, b1);
        float a0 = att[EMB + c];
        float a1 = (c + 1 < EMB) ? att[EMB + c + 1] : 0.0f;
        ahp[tid] = pack2(a0, a1);
    }
    if (tid < EMB) alo[tid] = att[tid];
    __syncthreads();

    const int row = blockIdx.x * blockDim.x + tid;
    if (row >= NNODE) return;

    // ---- nb row (packed accumulators, 36 channels incl. zero pad) ----
    unsigned long long acc[18];
#pragma unroll
    for (int i = 0; i < 18; i++) acc[i] = bp[i];

    const float* xr = fsrc + row * EMB;
    for (int k = 0; k < EMB; k++) {
        float xv = __ldg(xr + k);
        unsigned long long xx = pack2(xv, xv);
        const ulonglong2* wr = reinterpret_cast<const ulonglong2*>(Wsh + k * 36);
#pragma unroll
        for (int i = 0; i < 9; i++) {
            ulonglong2 wv = wr[i];
            FMA2(acc[2 * i],     wv.x, xx, acc[2 * i]);
            FMA2(acc[2 * i + 1], wv.y, xx, acc[2 * i + 1]);
        }
    }

    // ---- s_b = nb . att_hi (pad lanes are zero on both sides) ----
    unsigned long long sp = 0ull;  // (0.f, 0.f)
#pragma unroll
    for (int i = 0; i < 18; i++) FMA2(sp, acc[i], ahp[i], sp);
    float s0, s1;
    unpack2(sp, s0, s1);
    g_sb[jid][row] = s0 + s1;

    // ---- store padded nb row (18 x 8B stores, 8B aligned) ----
    unsigned long long* outr =
        reinterpret_cast<unsigned long long*>(&g_nb[jid][row * NBSTRIDE]);
#pragma unroll
    for (int i = 0; i < 18; i++) outr[i] = acc[i];

    // ---- s_a = fdst . att_lo ----
    const float* yr = fdst + row * EMB;
    float sa = 0.0f;
    for (int k = 0; k < EMB; k++) sa = fmaf(__ldg(yr + k), alo[k], sa);
    g_sa[jid][row] = sa;
}

// =====================================================================
// Kernel 2: attention aggregation. One warp per node (DEG==32 lanes).
// =====================================================================
__global__ __launch_bounds__(256) void agg_kernel(AArgs args) {
    const int jid = blockIdx.y;
    const float* __restrict__ nb  = g_nb[jid];
    const float* __restrict__ sbv = g_sb[jid];
    const float* __restrict__ sav = g_sa[jid];
    const int*   __restrict__ dst = args.dst[jid];
    float* __restrict__ m = g_m[jid];

    __shared__ float sw[8][32];
    __shared__ int   soff[8][32];

    const int wid  = threadIdx.x >> 5;
    const int lane = threadIdx.x & 31;
    const int node = blockIdx.x * 8 + wid;
    if (node >= NNODE) return;

    // phase 1: per-edge weight
    const int d = dst[node * DEG + lane];
    float x = sav[node] + sbv[d];
    float e = (x > 0.0f) ? x : 0.1f * expm1f(x);  // elu(alpha=0.1)
    float w = expf(e);

    float wsum = w;
#pragma unroll
    for (int o = 16; o; o >>= 1) wsum += __shfl_xor_sync(0xffffffffu, wsum, o);

    sw[wid][lane]   = w;
    soff[wid][lane] = d * NBSTRIDE;
    __syncwarp();

    // phase 2: lanes 0..17 each own a channel pair, loop over 32 edges
    if (lane < 18) {
        float ax = 0.0f, ay = 0.0f;
        const float* bp = nb + 2 * lane;
#pragma unroll
        for (int j = 0; j < 32; j++) {
            float wj  = sw[wid][j];
            int   off = soff[wid][j];
            float2 v = *reinterpret_cast<const float2*>(bp + off);
            ax = fmaf(wj, v.x, ax);
            ay = fmaf(wj, v.y, ay);
        }
        float inv = 1.0f / wsum;
        int c = 2 * lane;
        float* mr = m + node * EMB;
        mr[c] = ax * inv;
        if (c + 1 < EMB) mr[c + 1] = ay * inv;
    }
}

// =====================================================================
// Kernel 3: out = prelu([feat, m_pos, m_neg] @ W1 + b1) @ W2 + b2
// thread per node; weights in shared; packed f32x2 FMAs
// =====================================================================
__global__ __launch_bounds__(128) void update_kernel(
    const float* __restrict__ feat, int mbase,
    const float* __restrict__ W1, const float* __restrict__ b1,
    const float* __restrict__ alpha_p,
    const float* __restrict__ W2, const float* __restrict__ b2,
    float* __restrict__ out)
{
    __shared__ __align__(16) float W1sh[105 * 72];  // rows padded 70 -> 72
    __shared__ __align__(16) float W2sh[70 * 36];   // rows padded 35 -> 36
    __shared__ __align__(16) float b1sh[72];
    __shared__ __align__(16) float b2sh[36];

    const int tid = threadIdx.x;
    for (int i = tid; i < 105 * 72; i += blockDim.x) {
        int k = i / 72, c = i % 72;
        W1sh[i] = (c < 70) ? W1[k * 70 + c] : 0.0f;
    }
    for (int i = tid; i < 70 * 36; i += blockDim.x) {
        int k = i / 36, c = i % 36;
        W2sh[i] = (c < EMB) ? W2[k * EMB + c] : 0.0f;
    }
    if (tid < 72) b1sh[tid] = (tid < 70) ? b1[tid] : 0.0f;
    if (tid < 36) b2sh[tid] = (tid < EMB) ? b2[tid] : 0.0f;
    __syncthreads();

    const int node = blockIdx.x * blockDim.x + tid;
    if (node >= NNODE) return;

    const float alpha = __ldg(alpha_p);

    // ---- GEMM1: h = x @ W1 + b1, x = [feat | m_pos | m_neg] ----
    unsigned long long acc[36];
    const unsigned long long* b1p = reinterpret_cast<const unsigned long long*>(b1sh);
#pragma unroll
    for (int i = 0; i < 36; i++) acc[i] = b1p[i];

    const float* srcs[3] = { feat + node * EMB,
                             g_m[mbase]     + node * EMB,
                             g_m[mbase + 1] + node * EMB };
#pragma unroll 1
    for (int part = 0; part < 3; part++) {
        const float* xr = srcs[part];
        const float* wb = W1sh + part * EMB * 72;
        for (int k = 0; k < EMB; k++) {
            float xv = __ldg(xr + k);
            unsigned long long xx = pack2(xv, xv);
            const ulonglong2* wr = reinterpret_cast<const ulonglong2*>(wb + k * 72);
#pragma unroll
            for (int i = 0; i < 18; i++) {
                ulonglong2 wv = wr[i];
                FMA2(acc[2 * i],     wv.x, xx, acc[2 * i]);
                FMA2(acc[2 * i + 1], wv.y, xx, acc[2 * i + 1]);
            }
        }
    }

    // ---- PReLU -> h (local array; dynamically indexed in GEMM2) ----
    float h[70];
#pragma unroll
    for (int i = 0; i < 35; i++) {
        float h0, h1;
        unpack2(acc[i], h0, h1);
        h[2 * i]     = (h0 > 0.0f) ? h0 : alpha * h0;
        h[2 * i + 1] = (h1 > 0.0f) ? h1 : alpha * h1;
    }

    // ---- GEMM2: out = h @ W2 + b2 ----
    unsigned long long acc2[18];
    const unsigned long long* b2p = reinterpret_cast<const unsigned long long*>(b2sh);
#pragma unroll
    for (int i = 0; i < 18; i++) acc2[i] = b2p[i];

    for (int k = 0; k < 70; k++) {
        float hv = h[k];
        unsigned long long xx = pack2(hv, hv);
        const ulonglong2* wr = reinterpret_cast<const ulonglong2*>(W2sh + k * 36);
#pragma unroll
        for (int i = 0; i < 9; i++) {
            ulonglong2 wv = wr[i];
            FMA2(acc2[2 * i],     wv.x, xx, acc2[2 * i]);
            FMA2(acc2[2 * i + 1], wv.y, xx, acc2[2 * i + 1]);
        }
    }

    float* orow = out + node * EMB;
#pragma unroll
    for (int i = 0; i < 17; i++) {
        float o0, o1;
        unpack2(acc2[i], o0, o1);
        orow[2 * i]     = o0;
        orow[2 * i + 1] = o1;
    }
    {
        float o0, o1;
        unpack2(acc2[17], o0, o1);
        orow[34] = o0;  // channel 35 is pad
    }
}

// =====================================================================
// launch
// =====================================================================
extern "C" void kernel_launch(void* const* d_in, const int* in_sizes, int n_in,
                              void* d_out, int out_size) {
    const float* fa = (const float*)d_in[0];
    const float* fb = (const float*)d_in[1];

    TArgs t;
    // job order: 0=ab_pos, 1=ab_neg, 2=ba_pos, 3=ba_neg
    const float* fsrc[4] = { fb, fb, fa, fa };
    const float* fdst[4] = { fa, fa, fb, fb };
    for (int j = 0; j < 4; j++) {
        t.fsrc[j] = fsrc[j];
        t.fdst[j] = fdst[j];
        t.W[j]   = (const float*)d_in[6 + 3 * j];
        t.b[j]   = (const float*)d_in[7 + 3 * j];
        t.att[j] = (const float*)d_in[8 + 3 * j];
    }
    AArgs a;
    a.dst[0] = (const int*)d_in[2];
    a.dst[1] = (const int*)d_in[3];
    a.dst[2] = (const int*)d_in[4];
    a.dst[3] = (const int*)d_in[5];

    const float* W1 = (const float*)d_in[18];
    const float* b1 = (const float*)d_in[19];
    const float* al = (const float*)d_in[20];
    const float* W2 = (const float*)d_in[21];
    const float* b2 = (const float*)d_in[22];
    float* out = (float*)d_out;

    dim3 tg((NNODE + 127) / 128, 4);
    transform_kernel<<<tg, 128>>>(t);

    dim3 ag((NNODE + 7) / 8, 4);
    agg_kernel<<<ag, 256>>>(a);

    dim3 ug((NNODE + 127) / 128);
    update_kernel<<<ug, 128>>>(fa, 0, W1, b1, al, W2, b2, out);
    update_kernel<<<ug, 128>>>(fb, 2, W1, b1, al, W2, b2, out + NNODE * EMB);
}